// round 2
// baseline (speedup 1.0000x reference)
#include <cuda_runtime.h>

#define Bb   4
#define Nn   50000
#define Kk   128
#define Ss   256
#define KT   16                 // transforms per scoring block
#define PG   1024               // points per scoring block (256 thr * 4 pts)
#define NG   49                 // ceil(Nn / PG)
#define EPSF 1e-5f

// Scratch: reduction results, transforms, deterministic partial error sums
__device__ float g_sums[Bb * Kk * 16];        // [0..5]=centroids, [6..14]=H, [15]=unused
__device__ float g_transforms[Bb * Kk * 16];
__device__ float g_part[Bb * Kk * NG];

typedef unsigned long long u64;

__device__ __forceinline__ u64 pack2(float lo, float hi) {
    u64 r; asm("mov.b64 %0, {%1,%2};" : "=l"(r) : "f"(lo), "f"(hi)); return r;
}
__device__ __forceinline__ void unpack2(u64 v, float& lo, float& hi) {
    asm("mov.b64 {%0,%1}, %2;" : "=f"(lo), "=f"(hi) : "l"(v));
}
__device__ __forceinline__ u64 fma2(u64 a, u64 b, u64 c) {
    u64 d; asm("fma.rn.f32x2 %0, %1, %2, %3;" : "=l"(d) : "l"(a), "l"(b), "l"(c)); return d;
}
__device__ __forceinline__ u64 add2(u64 a, u64 b) {
    u64 d; asm("add.rn.f32x2 %0, %1, %2;" : "=l"(d) : "l"(a), "l"(b)); return d;
}
__device__ __forceinline__ u64 mul2(u64 a, u64 b) {
    u64 d; asm("mul.rn.f32x2 %0, %1, %2;" : "=l"(d) : "l"(a), "l"(b)); return d;
}

__device__ __forceinline__ float warp_sum(float v) {
#pragma unroll
    for (int o = 16; o; o >>= 1) v += __shfl_xor_sync(0xffffffffu, v, o);
    return v;
}

// ---------------------------------------------------------------------------
// Kernel 1a: per-(b,k) weighted sums -> centroids + covariance H (no serial tail)
// ---------------------------------------------------------------------------
__global__ void reduce_kernel(const float* __restrict__ src,
                              const float* __restrict__ tgt,
                              const float* __restrict__ wgt,
                              const int*   __restrict__ sel) {
    int bk = blockIdx.x;
    int b  = bk >> 7;
    int k  = bk & (Kk - 1);
    int s  = threadIdx.x;
    int lane = s & 31, wp = s >> 5;

    int idx = sel[k * Ss + s];
    int pb  = (b * Nn + idx) * 3;
    float sx = src[pb + 0], sy = src[pb + 1], sz = src[pb + 2];
    float tx = tgt[pb + 0], ty = tgt[pb + 1], tz = tgt[pb + 2];
    float ww = wgt[b * Nn + idx];

    __shared__ float red[9 * 8];
    __shared__ float sums[7];

    // phase 1: sumW + weighted centroids
    {
        float v[7] = {ww, ww * sx, ww * sy, ww * sz, ww * tx, ww * ty, ww * tz};
#pragma unroll
        for (int q = 0; q < 7; q++) {
            float r = warp_sum(v[q]);
            if (lane == 0) red[q * 8 + wp] = r;
        }
        __syncthreads();
        if (s < 7) {
            float a = 0.f;
#pragma unroll
            for (int i = 0; i < 8; i++) a += red[s * 8 + i];
            sums[s] = a;
        }
        __syncthreads();
    }
    float invW = 1.0f / (sums[0] + EPSF);
    float scx = sums[1] * invW, scy = sums[2] * invW, scz = sums[3] * invW;
    float tcx = sums[4] * invW, tcy = sums[5] * invW, tcz = sums[6] * invW;
    __syncthreads();

    // phase 2: H
    {
        float ax = sx - scx, ay = sy - scy, az = sz - scz;
        float bx = ww * (tx - tcx), by = ww * (ty - tcy), bz = ww * (tz - tcz);
        float v[9] = {ax * bx, ax * by, ax * bz,
                      ay * bx, ay * by, ay * bz,
                      az * bx, az * by, az * bz};
#pragma unroll
        for (int q = 0; q < 9; q++) {
            float r = warp_sum(v[q]);
            if (lane == 0) red[q * 8 + wp] = r;
        }
        __syncthreads();
        if (s < 9) {
            float a = 0.f;
#pragma unroll
            for (int i = 0; i < 8; i++) a += red[s * 8 + i];
            g_sums[bk * 16 + 6 + s] = a * invW;
        }
        if (s == 0) {
            float* o = g_sums + bk * 16;
            o[0] = scx; o[1] = scy; o[2] = scz;
            o[3] = tcx; o[4] = tcy; o[5] = tcz;
        }
    }
}

// ---------------------------------------------------------------------------
// Kernel 1b: one THREAD per hypothesis. Horn quaternion via 4x4 Jacobi.
// All 512 chains run in parallel (16 warps across SMs).
// ---------------------------------------------------------------------------
__global__ void jacobi_kernel() {
    int bk = blockIdx.x * blockDim.x + threadIdx.x;
    if (bk >= Bb * Kk) return;

    const float* in = g_sums + bk * 16;
    float scx = in[0], scy = in[1], scz = in[2];
    float tcx = in[3], tcy = in[4], tcz = in[5];
    float Sxx = in[6],  Sxy = in[7],  Sxz = in[8];
    float Syx = in[9],  Syy = in[10], Syz = in[11];
    float Szx = in[12], Szy = in[13], Szz = in[14];

    float A[4][4], V[4][4];
    A[0][0] = Sxx + Syy + Szz; A[0][1] = Syz - Szy; A[0][2] = Szx - Sxz; A[0][3] = Sxy - Syx;
    A[1][1] = Sxx - Syy - Szz; A[1][2] = Sxy + Syx; A[1][3] = Szx + Sxz;
    A[2][2] = -Sxx + Syy - Szz; A[2][3] = Syz + Szy;
    A[3][3] = -Sxx - Syy + Szz;
    A[1][0] = A[0][1]; A[2][0] = A[0][2]; A[3][0] = A[0][3];
    A[2][1] = A[1][2]; A[3][1] = A[1][3]; A[3][2] = A[2][3];
#pragma unroll
    for (int i = 0; i < 4; i++)
#pragma unroll
        for (int j = 0; j < 4; j++) V[i][j] = (i == j) ? 1.f : 0.f;

    for (int sweep = 0; sweep < 6; sweep++) {
#pragma unroll
        for (int p = 0; p < 3; p++) {
#pragma unroll
            for (int q = p + 1; q < 4; q++) {
                float apq = A[p][q];
                if (fabsf(apq) > 1e-20f) {
                    float tau = (A[q][q] - A[p][p]) / (2.0f * apq);
                    float tt  = (tau >= 0.f ? 1.f : -1.f) /
                                (fabsf(tau) + sqrtf(1.f + tau * tau));
                    float c = rsqrtf(1.f + tt * tt);
                    float sn = tt * c;
#pragma unroll
                    for (int m = 0; m < 4; m++) {
                        float amp = A[m][p], amq = A[m][q];
                        A[m][p] = c * amp - sn * amq;
                        A[m][q] = sn * amp + c * amq;
                    }
#pragma unroll
                    for (int m = 0; m < 4; m++) {
                        float apm = A[p][m], aqm = A[q][m];
                        A[p][m] = c * apm - sn * aqm;
                        A[q][m] = sn * apm + c * aqm;
                    }
#pragma unroll
                    for (int m = 0; m < 4; m++) {
                        float vmp = V[m][p], vmq = V[m][q];
                        V[m][p] = c * vmp - sn * vmq;
                        V[m][q] = sn * vmp + c * vmq;
                    }
                }
            }
        }
    }
    int jb = 0; float lb = A[0][0];
#pragma unroll
    for (int j = 1; j < 4; j++) { if (A[j][j] > lb) { lb = A[j][j]; jb = j; } }
    float qw = V[0][jb], qx = V[1][jb], qy = V[2][jb], qz = V[3][jb];
    float qn = rsqrtf(qw * qw + qx * qx + qy * qy + qz * qz);
    qw *= qn; qx *= qn; qy *= qn; qz *= qn;

    float R00 = 1.f - 2.f * (qy * qy + qz * qz), R01 = 2.f * (qx * qy - qw * qz), R02 = 2.f * (qx * qz + qw * qy);
    float R10 = 2.f * (qx * qy + qw * qz), R11 = 1.f - 2.f * (qx * qx + qz * qz), R12 = 2.f * (qy * qz - qw * qx);
    float R20 = 2.f * (qx * qz - qw * qy), R21 = 2.f * (qy * qz + qw * qx), R22 = 1.f - 2.f * (qx * qx + qy * qy);

    float t0 = tcx - (R00 * scx + R01 * scy + R02 * scz);
    float t1 = tcy - (R10 * scx + R11 * scy + R12 * scz);
    float t2 = tcz - (R20 * scx + R21 * scy + R22 * scz);

    float* T = g_transforms + bk * 16;
    T[0] = R00; T[1] = R01; T[2]  = R02; T[3]  = t0;
    T[4] = R10; T[5] = R11; T[6]  = R12; T[7]  = t1;
    T[8] = R20; T[9] = R21; T[10] = R22; T[11] = t2;
    T[12] = 0.f; T[13] = 0.f; T[14] = 0.f; T[15] = 1.f;
}

// ---------------------------------------------------------------------------
// Kernel 2: scoring with packed f32x2 math (2 points per FMA instruction).
// ---------------------------------------------------------------------------
__global__ void __launch_bounds__(256, 2)
score_kernel(const float* __restrict__ src,
             const float* __restrict__ tgt,
             const float* __restrict__ wgt) {
    int g = blockIdx.x, kt = blockIdx.y, b = blockIdx.z;
    int tid = threadIdx.x;

    __shared__ float sT[KT * 16];
    int tb = (b * Kk + kt * KT) * 16;
    for (int i = tid; i < KT * 16; i += 256) sT[i] = g_transforms[tb + i];
    __syncthreads();

    // load 4 points, pack as 2 pairs; targets pre-negated
    float px[4], py[4], pz[4], nqx[4], nqy[4], nqz[4], wv[4];
#pragma unroll
    for (int j = 0; j < 4; j++) {
        int p = g * PG + j * 256 + tid;
        if (p < Nn) {
            int pb = (b * Nn + p) * 3;
            wv[j] = wgt[b * Nn + p];
            px[j] = src[pb + 0]; py[j] = src[pb + 1]; pz[j] = src[pb + 2];
            nqx[j] = -tgt[pb + 0]; nqy[j] = -tgt[pb + 1]; nqz[j] = -tgt[pb + 2];
        } else {
            wv[j] = 0.f;
            px[j] = py[j] = pz[j] = 0.f;
            nqx[j] = nqy[j] = nqz[j] = 0.f;
        }
    }
    u64 PX[2], PY[2], PZ[2], NX[2], NY[2], NZ[2];
#pragma unroll
    for (int p = 0; p < 2; p++) {
        PX[p] = pack2(px[2*p], px[2*p+1]);
        PY[p] = pack2(py[2*p], py[2*p+1]);
        PZ[p] = pack2(pz[2*p], pz[2*p+1]);
        NX[p] = pack2(nqx[2*p], nqx[2*p+1]);
        NY[p] = pack2(nqy[2*p], nqy[2*p+1]);
        NZ[p] = pack2(nqz[2*p], nqz[2*p+1]);
    }

    float acc[KT];
#pragma unroll
    for (int kk = 0; kk < KT; kk++) acc[kk] = 0.f;

#pragma unroll
    for (int kk = 0; kk < KT; kk++) {
        float4 r0 = *(const float4*)&sT[kk * 16 + 0];
        float4 r1 = *(const float4*)&sT[kk * 16 + 4];
        float4 r2 = *(const float4*)&sT[kk * 16 + 8];
        u64 m00 = pack2(r0.x, r0.x), m01 = pack2(r0.y, r0.y), m02 = pack2(r0.z, r0.z);
        u64 m10 = pack2(r1.x, r1.x), m11 = pack2(r1.y, r1.y), m12 = pack2(r1.z, r1.z);
        u64 m20 = pack2(r2.x, r2.x), m21 = pack2(r2.y, r2.y), m22 = pack2(r2.z, r2.z);
        u64 t0  = pack2(r0.w, r0.w), t1  = pack2(r1.w, r1.w), t2  = pack2(r2.w, r2.w);
#pragma unroll
        for (int p = 0; p < 2; p++) {
            u64 dx = fma2(m00, PX[p], fma2(m01, PY[p], fma2(m02, PZ[p], add2(t0, NX[p]))));
            u64 dy = fma2(m10, PX[p], fma2(m11, PY[p], fma2(m12, PZ[p], add2(t1, NY[p]))));
            u64 dz = fma2(m20, PX[p], fma2(m21, PY[p], fma2(m22, PZ[p], add2(t2, NZ[p]))));
            u64 d2 = fma2(dx, dx, fma2(dy, dy, mul2(dz, dz)));
            float d2lo, d2hi;
            unpack2(d2, d2lo, d2hi);
            float e0, e1;
            asm("sqrt.approx.f32 %0, %1;" : "=f"(e0) : "f"(d2lo));
            asm("sqrt.approx.f32 %0, %1;" : "=f"(e1) : "f"(d2hi));
            acc[kk] = fmaf(wv[2*p], e0, acc[kk]);
            acc[kk] = fmaf(wv[2*p+1], e1, acc[kk]);
        }
    }

    // block-reduce 16 accumulators, deterministic partials
    __shared__ float red[KT * 8];
    int lane = tid & 31, wp = tid >> 5;
#pragma unroll
    for (int kk = 0; kk < KT; kk++) {
        float v = warp_sum(acc[kk]);
        if (lane == 0) red[kk * 8 + wp] = v;
    }
    __syncthreads();
    if (tid < KT) {
        float s = 0.f;
#pragma unroll
        for (int i = 0; i < 8; i++) s += red[tid * 8 + i];
        g_part[(b * Kk + kt * KT + tid) * NG + g] = s;
    }
}

// ---------------------------------------------------------------------------
// Kernel 3: per-batch argmin over K and emit best transform.
// ---------------------------------------------------------------------------
__global__ void pick_kernel(float* __restrict__ out) {
    int b = blockIdx.x;
    int k = threadIdx.x;

    float s = 0.f;
    const float* p = g_part + (b * Kk + k) * NG;
    for (int g = 0; g < NG; g++) s += p[g];

    float best = s; int bi = k;
#pragma unroll
    for (int o = 16; o; o >>= 1) {
        float oe = __shfl_xor_sync(0xffffffffu, best, o);
        int   oi = __shfl_xor_sync(0xffffffffu, bi, o);
        if (oe < best || (oe == best && oi < bi)) { best = oe; bi = oi; }
    }
    __shared__ float wb[4];
    __shared__ int   wi[4];
    __shared__ int   sk;
    int lane = k & 31, wp = k >> 5;
    if (lane == 0) { wb[wp] = best; wi[wp] = bi; }
    __syncthreads();
    if (k == 0) {
        float bb = wb[0]; int ii = wi[0];
#pragma unroll
        for (int i = 1; i < 4; i++)
            if (wb[i] < bb || (wb[i] == bb && wi[i] < ii)) { bb = wb[i]; ii = wi[i]; }
        sk = ii;
    }
    __syncthreads();
    if (k < 16) out[b * 16 + k] = g_transforms[(b * Kk + sk) * 16 + k];
}

// ---------------------------------------------------------------------------
extern "C" void kernel_launch(void* const* d_in, const int* in_sizes, int n_in,
                              void* d_out, int out_size) {
    const float* src = (const float*)d_in[0];
    const float* tgt = (const float*)d_in[1];
    const float* wgt = (const float*)d_in[2];
    const int*   sel = (const int*)d_in[3];
    float* out = (float*)d_out;

    reduce_kernel<<<Bb * Kk, Ss>>>(src, tgt, wgt, sel);
    jacobi_kernel<<<4, 128>>>();
    dim3 grid2(NG, Kk / KT, Bb);
    score_kernel<<<grid2, 256>>>(src, tgt, wgt);
    pick_kernel<<<Bb, 128>>>(out);
}

// round 3
// speedup vs baseline: 1.1173x; 1.1173x over previous
#include <cuda_runtime.h>

#define Bb   4
#define Nn   50000
#define Kk   128
#define Ss   256
#define KT   16                 // transforms per scoring block
#define PTS  8                  // points per thread
#define PG   2048               // points per scoring block (256 thr * 8 pts)
#define NG   25                 // ceil(Nn / PG)
#define NBLK (NG * (Kk / KT) * Bb)   // 800 scoring blocks
#define EPSF 1e-5f

__device__ float g_transforms[Bb * Kk * 16];
__device__ float g_part[NG * Bb * Kk];       // g-major: [g][bk]
__device__ unsigned int g_cnt = 0;

typedef unsigned long long u64;

__device__ __forceinline__ u64 pack2(float lo, float hi) {
    u64 r; asm("mov.b64 %0, {%1,%2};" : "=l"(r) : "f"(lo), "f"(hi)); return r;
}
__device__ __forceinline__ void unpack2(u64 v, float& lo, float& hi) {
    asm("mov.b64 {%0,%1}, %2;" : "=f"(lo), "=f"(hi) : "l"(v));
}
__device__ __forceinline__ u64 fma2(u64 a, u64 b, u64 c) {
    u64 d; asm("fma.rn.f32x2 %0, %1, %2, %3;" : "=l"(d) : "l"(a), "l"(b), "l"(c)); return d;
}
__device__ __forceinline__ u64 add2(u64 a, u64 b) {
    u64 d; asm("add.rn.f32x2 %0, %1, %2;" : "=l"(d) : "l"(a), "l"(b)); return d;
}
__device__ __forceinline__ u64 mul2(u64 a, u64 b) {
    u64 d; asm("mul.rn.f32x2 %0, %1, %2;" : "=l"(d) : "l"(a), "l"(b)); return d;
}
__device__ __forceinline__ float frcp(float x)   { float r; asm("rcp.approx.f32 %0,%1;"   : "=f"(r) : "f"(x)); return r; }
__device__ __forceinline__ float fsqrta(float x) { float r; asm("sqrt.approx.f32 %0,%1;"  : "=f"(r) : "f"(x)); return r; }
__device__ __forceinline__ float frsqrt(float x) { float r; asm("rsqrt.approx.f32 %0,%1;" : "=f"(r) : "f"(x)); return r; }

__device__ __forceinline__ float warp_sum(float v) {
#pragma unroll
    for (int o = 16; o; o >>= 1) v += __shfl_xor_sync(0xffffffffu, v, o);
    return v;
}

// ---------------------------------------------------------------------------
// Kernel 1: fused per-(b,k) reduction (single pass, raw moments) + Horn
// quaternion (4x4 Jacobi, approx math) on thread 0. 512 blocks x 256 thr.
// ---------------------------------------------------------------------------
__global__ void procrustes_fused_kernel(const float* __restrict__ src,
                                        const float* __restrict__ tgt,
                                        const float* __restrict__ wgt,
                                        const int*   __restrict__ sel) {
    int bk = blockIdx.x;
    int b  = bk >> 7;
    int k  = bk & (Kk - 1);
    int s  = threadIdx.x;
    int lane = s & 31, wp = s >> 5;

    int idx = sel[k * Ss + s];
    int pb  = (b * Nn + idx) * 3;
    float sx = src[pb + 0], sy = src[pb + 1], sz = src[pb + 2];
    float tx = tgt[pb + 0], ty = tgt[pb + 1], tz = tgt[pb + 2];
    float ww = wgt[b * Nn + idx];

    __shared__ float red[16 * 8];
    __shared__ float sums[16];

    // single-pass: w, w*s, w*t, w*s_i*t_j  (16 reductions, no mid barrier)
    {
        float wsx = ww * sx, wsy = ww * sy, wsz = ww * sz;
        float v[16] = {ww, wsx, wsy, wsz, ww * tx, ww * ty, ww * tz,
                       wsx * tx, wsx * ty, wsx * tz,
                       wsy * tx, wsy * ty, wsy * tz,
                       wsz * tx, wsz * ty, wsz * tz};
#pragma unroll
        for (int q = 0; q < 16; q++) {
            float r = warp_sum(v[q]);
            if (lane == 0) red[q * 8 + wp] = r;
        }
        __syncthreads();
        if (s < 16) {
            float a = 0.f;
#pragma unroll
            for (int i = 0; i < 8; i++) a += red[s * 8 + i];
            sums[s] = a;
        }
        __syncthreads();
    }

    if (s == 0) {
        float W    = sums[0];
        float invW = 1.0f / (W + EPSF);
        float sig  = W * invW;
        float scx = sums[1] * invW, scy = sums[2] * invW, scz = sums[3] * invW;
        float tcx = sums[4] * invW, tcy = sums[5] * invW, tcz = sums[6] * invW;
        float c2  = 2.0f - sig;
        // H = M/W - (2-sigma) * s_c t_c^T
        float Sxx = sums[7]  * invW - c2 * scx * tcx;
        float Sxy = sums[8]  * invW - c2 * scx * tcy;
        float Sxz = sums[9]  * invW - c2 * scx * tcz;
        float Syx = sums[10] * invW - c2 * scy * tcx;
        float Syy = sums[11] * invW - c2 * scy * tcy;
        float Syz = sums[12] * invW - c2 * scy * tcz;
        float Szx = sums[13] * invW - c2 * scz * tcx;
        float Szy = sums[14] * invW - c2 * scz * tcy;
        float Szz = sums[15] * invW - c2 * scz * tcz;

        float A[4][4], V[4][4];
        A[0][0] = Sxx + Syy + Szz; A[0][1] = Syz - Szy; A[0][2] = Szx - Sxz; A[0][3] = Sxy - Syx;
        A[1][1] = Sxx - Syy - Szz; A[1][2] = Sxy + Syx; A[1][3] = Szx + Sxz;
        A[2][2] = -Sxx + Syy - Szz; A[2][3] = Syz + Szy;
        A[3][3] = -Sxx - Syy + Szz;
        A[1][0] = A[0][1]; A[2][0] = A[0][2]; A[3][0] = A[0][3];
        A[2][1] = A[1][2]; A[3][1] = A[1][3]; A[3][2] = A[2][3];
#pragma unroll
        for (int i = 0; i < 4; i++)
#pragma unroll
            for (int j = 0; j < 4; j++) V[i][j] = (i == j) ? 1.f : 0.f;

        for (int sweep = 0; sweep < 6; sweep++) {
#pragma unroll
            for (int p = 0; p < 3; p++) {
#pragma unroll
                for (int q = p + 1; q < 4; q++) {
                    float apq = A[p][q];
                    if (fabsf(apq) > 1e-20f) {
                        float tau = (A[q][q] - A[p][p]) * 0.5f * frcp(apq);
                        float tt  = (tau >= 0.f ? 1.f : -1.f) *
                                    frcp(fabsf(tau) + fsqrta(fmaf(tau, tau, 1.f)));
                        float c = frsqrt(fmaf(tt, tt, 1.f));
                        float sn = tt * c;
#pragma unroll
                        for (int m = 0; m < 4; m++) {
                            float amp = A[m][p], amq = A[m][q];
                            A[m][p] = c * amp - sn * amq;
                            A[m][q] = sn * amp + c * amq;
                        }
#pragma unroll
                        for (int m = 0; m < 4; m++) {
                            float apm = A[p][m], aqm = A[q][m];
                            A[p][m] = c * apm - sn * aqm;
                            A[q][m] = sn * apm + c * aqm;
                        }
#pragma unroll
                        for (int m = 0; m < 4; m++) {
                            float vmp = V[m][p], vmq = V[m][q];
                            V[m][p] = c * vmp - sn * vmq;
                            V[m][q] = sn * vmp + c * vmq;
                        }
                    }
                }
            }
        }
        int jb = 0; float lb = A[0][0];
#pragma unroll
        for (int j = 1; j < 4; j++) { if (A[j][j] > lb) { lb = A[j][j]; jb = j; } }
        float qw = V[0][jb], qx = V[1][jb], qy = V[2][jb], qz = V[3][jb];
        float qn = frsqrt(qw * qw + qx * qx + qy * qy + qz * qz);
        qw *= qn; qx *= qn; qy *= qn; qz *= qn;

        float R00 = 1.f - 2.f * (qy * qy + qz * qz), R01 = 2.f * (qx * qy - qw * qz), R02 = 2.f * (qx * qz + qw * qy);
        float R10 = 2.f * (qx * qy + qw * qz), R11 = 1.f - 2.f * (qx * qx + qz * qz), R12 = 2.f * (qy * qz - qw * qx);
        float R20 = 2.f * (qx * qz - qw * qy), R21 = 2.f * (qy * qz + qw * qx), R22 = 1.f - 2.f * (qx * qx + qy * qy);

        float t0 = tcx - (R00 * scx + R01 * scy + R02 * scz);
        float t1 = tcy - (R10 * scx + R11 * scy + R12 * scz);
        float t2 = tcz - (R20 * scx + R21 * scy + R22 * scz);

        float* T = g_transforms + bk * 16;
        T[0] = R00; T[1] = R01; T[2]  = R02; T[3]  = t0;
        T[4] = R10; T[5] = R11; T[6]  = R12; T[7]  = t1;
        T[8] = R20; T[9] = R21; T[10] = R22; T[11] = t2;
        T[12] = 0.f; T[13] = 0.f; T[14] = 0.f; T[15] = 1.f;
    }
}

// ---------------------------------------------------------------------------
// Kernel 2: scoring (f32x2, 8 points/thread, 16 transforms/block) with fused
// final argmin in the last-finishing block (threadfence + counter pattern).
// ---------------------------------------------------------------------------
__global__ void __launch_bounds__(256, 2)
score_pick_kernel(const float* __restrict__ src,
                  const float* __restrict__ tgt,
                  const float* __restrict__ wgt,
                  float* __restrict__ out) {
    int g = blockIdx.x, kt = blockIdx.y, b = blockIdx.z;
    int tid = threadIdx.x;
    int lane = tid & 31, wp = tid >> 5;

    __shared__ float sT[KT * 16];
    int tb = (b * Kk + kt * KT) * 16;
    for (int i = tid; i < KT * 16; i += 256) sT[i] = g_transforms[tb + i];
    __syncthreads();

    // load 8 points; pack as 4 f32x2 pairs; targets pre-negated
    float px[PTS], py[PTS], pz[PTS], wv[PTS];
    float nx[PTS], ny[PTS], nz[PTS];
#pragma unroll
    for (int j = 0; j < PTS; j++) {
        int p = g * PG + j * 256 + tid;
        if (p < Nn) {
            int pb = (b * Nn + p) * 3;
            wv[j] = wgt[b * Nn + p];
            px[j] = src[pb + 0]; py[j] = src[pb + 1]; pz[j] = src[pb + 2];
            nx[j] = -tgt[pb + 0]; ny[j] = -tgt[pb + 1]; nz[j] = -tgt[pb + 2];
        } else {
            wv[j] = 0.f; px[j] = py[j] = pz[j] = 0.f;
            nx[j] = ny[j] = nz[j] = 0.f;
        }
    }
    u64 PX[4], PY[4], PZ[4], NX[4], NY[4], NZ[4];
#pragma unroll
    for (int p = 0; p < 4; p++) {
        PX[p] = pack2(px[2*p], px[2*p+1]);
        PY[p] = pack2(py[2*p], py[2*p+1]);
        PZ[p] = pack2(pz[2*p], pz[2*p+1]);
        NX[p] = pack2(nx[2*p], nx[2*p+1]);
        NY[p] = pack2(ny[2*p], ny[2*p+1]);
        NZ[p] = pack2(nz[2*p], nz[2*p+1]);
    }

    float acc[KT];
#pragma unroll
    for (int kk = 0; kk < KT; kk++) acc[kk] = 0.f;

#pragma unroll
    for (int kk = 0; kk < KT; kk++) {
        float4 r0 = *(const float4*)&sT[kk * 16 + 0];
        float4 r1 = *(const float4*)&sT[kk * 16 + 4];
        float4 r2 = *(const float4*)&sT[kk * 16 + 8];
        u64 m00 = pack2(r0.x, r0.x), m01 = pack2(r0.y, r0.y), m02 = pack2(r0.z, r0.z);
        u64 m10 = pack2(r1.x, r1.x), m11 = pack2(r1.y, r1.y), m12 = pack2(r1.z, r1.z);
        u64 m20 = pack2(r2.x, r2.x), m21 = pack2(r2.y, r2.y), m22 = pack2(r2.z, r2.z);
        u64 t0  = pack2(r0.w, r0.w), t1  = pack2(r1.w, r1.w), t2  = pack2(r2.w, r2.w);
        float a = acc[kk];
#pragma unroll
        for (int p = 0; p < 4; p++) {
            u64 dx = fma2(m00, PX[p], fma2(m01, PY[p], fma2(m02, PZ[p], add2(t0, NX[p]))));
            u64 dy = fma2(m10, PX[p], fma2(m11, PY[p], fma2(m12, PZ[p], add2(t1, NY[p]))));
            u64 dz = fma2(m20, PX[p], fma2(m21, PY[p], fma2(m22, PZ[p], add2(t2, NZ[p]))));
            u64 d2 = fma2(dx, dx, fma2(dy, dy, mul2(dz, dz)));
            float d2lo, d2hi;
            unpack2(d2, d2lo, d2hi);
            a = fmaf(wv[2*p],     fsqrta(d2lo), a);
            a = fmaf(wv[2*p + 1], fsqrta(d2hi), a);
        }
        acc[kk] = a;
    }

    // block-reduce 16 accumulators, write g-major partials
    __shared__ float red[KT * 8];
#pragma unroll
    for (int kk = 0; kk < KT; kk++) {
        float v = warp_sum(acc[kk]);
        if (lane == 0) red[kk * 8 + wp] = v;
    }
    __syncthreads();
    if (tid < KT) {
        float s = 0.f;
#pragma unroll
        for (int i = 0; i < 8; i++) s += red[tid * 8 + i];
        g_part[g * (Bb * Kk) + (b * Kk + kt * KT + tid)] = s;
    }

    // ---- last-block argmin + emit ----
    __threadfence();
    __shared__ unsigned s_old;
    if (tid == 0) s_old = atomicAdd(&g_cnt, 1u);
    __syncthreads();
    if (s_old != NBLK - 1) return;
    __threadfence();

    __shared__ float s_err[Bb * Kk];
    {
        float s0 = 0.f, s1 = 0.f;
#pragma unroll
        for (int gg = 0; gg < NG; gg++) {
            s0 += __ldcg(&g_part[gg * (Bb * Kk) + tid]);
            s1 += __ldcg(&g_part[gg * (Bb * Kk) + tid + 256]);
        }
        s_err[tid] = s0;
        s_err[tid + 256] = s1;
    }
    __syncthreads();

    if (wp < Bb) {   // warp wp handles batch wp
        int bb = wp;
        float best = 1e30f; int bi = 0;
#pragma unroll
        for (int r = 0; r < 4; r++) {
            int k = r * 32 + lane;                 // increasing k within lane
            float v = s_err[bb * Kk + k];
            if (v < best) { best = v; bi = k; }
        }
#pragma unroll
        for (int o = 16; o; o >>= 1) {
            float oe = __shfl_xor_sync(0xffffffffu, best, o);
            int   oi = __shfl_xor_sync(0xffffffffu, bi, o);
            if (oe < best || (oe == best && oi < bi)) { best = oe; bi = oi; }
        }
        int bk = bb * Kk + __shfl_sync(0xffffffffu, bi, 0);
        if (lane < 16)
            out[bb * 16 + lane] = __ldcg(&g_transforms[bk * 16 + lane]);
    }
    if (tid == 0) g_cnt = 0;   // reset for next graph replay
}

// ---------------------------------------------------------------------------
extern "C" void kernel_launch(void* const* d_in, const int* in_sizes, int n_in,
                              void* d_out, int out_size) {
    const float* src = (const float*)d_in[0];
    const float* tgt = (const float*)d_in[1];
    const float* wgt = (const float*)d_in[2];
    const int*   sel = (const int*)d_in[3];
    float* out = (float*)d_out;

    procrustes_fused_kernel<<<Bb * Kk, Ss>>>(src, tgt, wgt, sel);
    dim3 grid2(NG, Kk / KT, Bb);
    score_pick_kernel<<<grid2, 256>>>(src, tgt, wgt, out);
}